// round 9
// baseline (speedup 1.0000x reference)
#include <cuda_runtime.h>
#include <cuda_bf16.h>

#define Bn 4
#define Sn 4096
#define Hn 2048
#define H4 (Hn / 4)
#define EPSf 1e-6f

#define BPB 64              // rows per block (single-wave grid: 256 blocks)
#define CS 16               // rows per chunk == warps per block
#define NCH (BPB / CS)      // 4 chunks

__device__ __forceinline__ float warp_sum(float v) {
#pragma unroll
    for (int o = 16; o; o >>= 1)
        v += __shfl_xor_sync(0xFFFFFFFFu, v, o);
    return v;
}

__device__ __forceinline__ float dot4(const float4 v) {
    return fmaf(v.x, v.x, fmaf(v.y, v.y, fmaf(v.z, v.z, v.w * v.w)));
}

// ---------------------------------------------------------------------------
// Fused RMSNorm + depthwise causal conv1d (K=4) + bias.
// grid = (S/BPB, B) = 256 blocks (single wave at occ 2), block = 512.
// Block owns 64 consecutive rows = 4 chunks of 16. Per chunk:
//   P1: warp w full-row-reduces row sb+w (balanced, 16-deep load stream)
//       -> inv_rms into ping-pong smem. One barrier.
//   P2: 512 threads, one float4 H-column each, rolling 3-deep window (L2
//       re-read), folded taps, streaming stores. Window carries across chunks
//       in registers -> halo handled once per block.
// ---------------------------------------------------------------------------
__global__ __launch_bounds__(512, 2) void fused_kernel(const float* __restrict__ x,
                                                       const float* __restrict__ nw,
                                                       const float* __restrict__ cw,
                                                       const float* __restrict__ cb,
                                                       float*       __restrict__ out) {
    __shared__ float s_ir[2][CS];   // ping-pong per-chunk inv_rms
    __shared__ float s_hir[3];      // halo inv_rms (block prologue only)

    const int b    = blockIdx.y;
    const int s0   = blockIdx.x * BPB;
    const int tid  = threadIdx.x;
    const int warp = tid >> 5;
    const int lane = tid & 31;

    const float* xb = x   + (size_t)b * Sn * Hn;
    float*       ob = out + (size_t)b * Sn * Hn;

    // ---- prologue: halo inv_rms for rows s0-3..s0-1 (warps 0..2) ----
    if (warp < 3) {
        const int s = s0 - 3 + warp;
        float a0 = 0.f, a1 = 0.f;
        if (s >= 0) {
            const float4* xr = reinterpret_cast<const float4*>(xb + (size_t)s * Hn);
#pragma unroll
            for (int i = 0; i < 16; i += 2) {
                float4 v0 = xr[lane + 32 * (i + 0)];
                float4 v1 = xr[lane + 32 * (i + 1)];
                a0 += dot4(v0);
                a1 += dot4(v1);
            }
        }
        float ss = warp_sum(a0 + a1);
        if (lane == 0)
            s_hir[warp] = (s >= 0) ? rsqrtf(ss * (1.0f / (float)Hn) + EPSf) : 0.0f;
    }

    // ---- per-thread constants: taps (norm_weight folded), bias ----
    const int h4 = tid;
    const int h  = h4 * 4;
    const float4* cw4 = reinterpret_cast<const float4*>(cw);
    const float4 nwv = __ldg(&reinterpret_cast<const float4*>(nw)[h4]);
    float4 t0 = __ldg(&cw4[h + 0]);
    float4 t1 = __ldg(&cw4[h + 1]);
    float4 t2 = __ldg(&cw4[h + 2]);
    float4 t3 = __ldg(&cw4[h + 3]);
    t0.x *= nwv.x; t0.y *= nwv.x; t0.z *= nwv.x; t0.w *= nwv.x;
    t1.x *= nwv.y; t1.y *= nwv.y; t1.z *= nwv.y; t1.w *= nwv.y;
    t2.x *= nwv.z; t2.y *= nwv.z; t2.z *= nwv.z; t2.w *= nwv.z;
    t3.x *= nwv.w; t3.y *= nwv.w; t3.z *= nwv.w; t3.w *= nwv.w;
    const float4 bias = __ldg(&reinterpret_cast<const float4*>(cb)[h4]);

    __syncthreads();

    // ---- rolling window from halo rows ----
    float4 xm3, xm2, xm1;
    {
        float4 pre[3];
#pragma unroll
        for (int j = 0; j < 3; j++) {
            const int s = s0 - 3 + j;
            if (s >= 0) {
                float4 v = reinterpret_cast<const float4*>(xb + (size_t)s * Hn)[h4];
                const float r = s_hir[j];
                pre[j].x = v.x * r; pre[j].y = v.y * r; pre[j].z = v.z * r; pre[j].w = v.w * r;
            } else {
                pre[j] = make_float4(0.f, 0.f, 0.f, 0.f);
            }
        }
        xm3 = pre[0]; xm2 = pre[1]; xm1 = pre[2];
    }

    // ---- main loop: 4 chunks of 16 rows ----
#pragma unroll 1
    for (int c = 0; c < NCH; c++) {
        const int sb = s0 + c * CS;

        // P1: warp w reduces row sb+w (full row, 16-deep independent loads)
        {
            const float4* xr = reinterpret_cast<const float4*>(xb + (size_t)(sb + warp) * Hn);
            float a0 = 0.f, a1 = 0.f;
#pragma unroll
            for (int i = 0; i < 16; i += 2) {
                float4 v0 = xr[lane + 32 * (i + 0)];
                float4 v1 = xr[lane + 32 * (i + 1)];
                a0 += dot4(v0);
                a1 += dot4(v1);
            }
            float ss = warp_sum(a0 + a1);
            if (lane == 0)
                s_ir[c & 1][warp] = rsqrtf(ss * (1.0f / (float)Hn) + EPSf);
        }
        __syncthreads();

        // P2: conv rows sb..sb+15 (x re-read hits L2)
        const float* irc = s_ir[c & 1];
#pragma unroll 4
        for (int j = 0; j < CS; j++) {
            const int s = sb + j;
            float4 v = reinterpret_cast<const float4*>(xb + (size_t)s * Hn)[h4];
            const float r = irc[j];
            float4 xn;
            xn.x = v.x * r;
            xn.y = v.y * r;
            xn.z = v.z * r;
            xn.w = v.w * r;

            float4 y;
            y.x = fmaf(t0.x, xm3.x, fmaf(t0.y, xm2.x, fmaf(t0.z, xm1.x, fmaf(t0.w, xn.x, bias.x))));
            y.y = fmaf(t1.x, xm3.y, fmaf(t1.y, xm2.y, fmaf(t1.z, xm1.y, fmaf(t1.w, xn.y, bias.y))));
            y.z = fmaf(t2.x, xm3.z, fmaf(t2.y, xm2.z, fmaf(t2.z, xm1.z, fmaf(t2.w, xn.z, bias.z))));
            y.w = fmaf(t3.x, xm3.w, fmaf(t3.y, xm2.w, fmaf(t3.z, xm1.w, fmaf(t3.w, xn.w, bias.w))));

            __stcs(reinterpret_cast<float4*>(ob + (size_t)s * Hn) + h4, y);

            xm3 = xm2; xm2 = xm1; xm1 = xn;
        }
        // one barrier per chunk is enough: s_ir is ping-ponged, and the next
        // overwrite of this buffer (chunk c+2) sits behind chunk c+1's barrier.
    }
}

// ---------------------------------------------------------------------------
// Inputs (metadata order): hidden_states, norm_weight, conv_weight, conv_bias
// ---------------------------------------------------------------------------
extern "C" void kernel_launch(void* const* d_in, const int* in_sizes, int n_in,
                              void* d_out, int out_size) {
    const float* x  = (const float*)d_in[0];
    const float* nw = (const float*)d_in[1];
    const float* cw = (const float*)d_in[2];
    const float* cb = (const float*)d_in[3];
    float* out = (float*)d_out;

    dim3 grid(Sn / BPB, Bn);   // (64, 4) = 256 blocks: single wave at occ 2
    fused_kernel<<<grid, 512>>>(x, nw, cw, cb, out);
}

// round 10
// speedup vs baseline: 1.0770x; 1.0770x over previous
#include <cuda_runtime.h>
#include <cuda_bf16.h>

#define Bn 4
#define Sn 4096
#define Hn 2048
#define H4 (Hn / 4)
#define EPSf 1e-6f

#define CS 8                // s-rows produced per block
#define NROWS (CS + 3)      // 11 rows incl. causal halo
#define SMEM_BYTES (NROWS * H4 * 16 + 64)

__device__ __forceinline__ float warp_sum(float v) {
#pragma unroll
    for (int o = 16; o; o >>= 1)
        v += __shfl_xor_sync(0xFFFFFFFFu, v, o);
    return v;
}

__device__ __forceinline__ float dot4(const float4 v) {
    return fmaf(v.x, v.x, fmaf(v.y, v.y, fmaf(v.z, v.z, v.w * v.w)));
}

// ---------------------------------------------------------------------------
// Fused RMSNorm + depthwise causal conv1d (K=4) + bias, smem-resident tile.
// grid = (S/CS, B) = 2048 blocks, block = 512, 88KB dyn smem, occ 2.
// Phase 1: warp w (w<11) streams row s0-3+w from GMEM (16 independent
//          LDG.128), stashing each float4 into smem while accumulating the
//          sq-sum -> inv_rms. One barrier.
// Phase 2: 512 threads, one float4 H-column, rolling 3-deep window; all row
//          reads are LDS (29cyc) instead of L2 (~250cyc). Folded taps, stcs.
// ---------------------------------------------------------------------------
__global__ __launch_bounds__(512, 2) void fused_kernel(const float* __restrict__ x,
                                                       const float* __restrict__ nw,
                                                       const float* __restrict__ cw,
                                                       const float* __restrict__ cb,
                                                       float*       __restrict__ out) {
    extern __shared__ float4 buf[];                   // [NROWS][H4]
    __shared__ float s_ir[NROWS];

    const int b    = blockIdx.y;
    const int s0   = blockIdx.x * CS;
    const int tid  = threadIdx.x;
    const int warp = tid >> 5;
    const int lane = tid & 31;

    const float* xb = x   + (size_t)b * Sn * Hn;
    float*       ob = out + (size_t)b * Sn * Hn;

    // ---- Phase 1: stream + stash + reduce (one row per warp, 11 warps) ----
    if (warp < NROWS) {
        const int s = s0 - 3 + warp;
        float4* dst = buf + warp * H4;
        float a0 = 0.f, a1 = 0.f;
        if (s >= 0) {
            const float4* xr = reinterpret_cast<const float4*>(xb + (size_t)s * Hn);
#pragma unroll
            for (int i = 0; i < 16; i += 2) {
                float4 v0 = xr[lane + 32 * (i + 0)];
                float4 v1 = xr[lane + 32 * (i + 1)];
                dst[lane + 32 * (i + 0)] = v0;
                dst[lane + 32 * (i + 1)] = v1;
                a0 += dot4(v0);
                a1 += dot4(v1);
            }
        } else {
            const float4 z = make_float4(0.f, 0.f, 0.f, 0.f);
#pragma unroll
            for (int i = 0; i < 16; i++)
                dst[lane + 32 * i] = z;
        }
        float ss = warp_sum(a0 + a1);
        if (lane == 0)
            s_ir[warp] = (s >= 0) ? rsqrtf(ss * (1.0f / (float)Hn) + EPSf) : 0.0f;
    }

    // ---- per-thread constants while phase-1 loads are in flight ----
    const int h4 = tid;
    const int h  = h4 * 4;
    const float4* cw4 = reinterpret_cast<const float4*>(cw);
    const float4 nwv = __ldg(&reinterpret_cast<const float4*>(nw)[h4]);
    float4 t0 = __ldg(&cw4[h + 0]);
    float4 t1 = __ldg(&cw4[h + 1]);
    float4 t2 = __ldg(&cw4[h + 2]);
    float4 t3 = __ldg(&cw4[h + 3]);
    t0.x *= nwv.x; t0.y *= nwv.x; t0.z *= nwv.x; t0.w *= nwv.x;
    t1.x *= nwv.y; t1.y *= nwv.y; t1.z *= nwv.y; t1.w *= nwv.y;
    t2.x *= nwv.z; t2.y *= nwv.z; t2.z *= nwv.z; t2.w *= nwv.z;
    t3.x *= nwv.w; t3.y *= nwv.w; t3.z *= nwv.w; t3.w *= nwv.w;
    const float4 bias = __ldg(&reinterpret_cast<const float4*>(cb)[h4]);

    __syncthreads();

    // ---- Phase 2: conv from smem ----
    float4 xm3, xm2, xm1;
    {
#pragma unroll
        for (int j = 0; j < 3; j++) {
            float4 v = buf[j * H4 + h4];
            const float r = s_ir[j];
            float4 p;
            p.x = v.x * r; p.y = v.y * r; p.z = v.z * r; p.w = v.w * r;
            if (j == 0) xm3 = p;
            else if (j == 1) xm2 = p;
            else xm1 = p;
        }
    }

#pragma unroll 4
    for (int j = 0; j < CS; j++) {
        float4 v = buf[(j + 3) * H4 + h4];
        const float r = s_ir[j + 3];
        float4 xn;
        xn.x = v.x * r;
        xn.y = v.y * r;
        xn.z = v.z * r;
        xn.w = v.w * r;

        float4 y;
        y.x = fmaf(t0.x, xm3.x, fmaf(t0.y, xm2.x, fmaf(t0.z, xm1.x, fmaf(t0.w, xn.x, bias.x))));
        y.y = fmaf(t1.x, xm3.y, fmaf(t1.y, xm2.y, fmaf(t1.z, xm1.y, fmaf(t1.w, xn.y, bias.y))));
        y.z = fmaf(t2.x, xm3.z, fmaf(t2.y, xm2.z, fmaf(t2.z, xm1.z, fmaf(t2.w, xn.z, bias.z))));
        y.w = fmaf(t3.x, xm3.w, fmaf(t3.y, xm2.w, fmaf(t3.z, xm1.w, fmaf(t3.w, xn.w, bias.w))));

        __stcs(reinterpret_cast<float4*>(ob + (size_t)(s0 + j) * Hn) + h4, y);

        xm3 = xm2; xm2 = xm1; xm1 = xn;
    }
}

// ---------------------------------------------------------------------------
// Inputs (metadata order): hidden_states, norm_weight, conv_weight, conv_bias
// ---------------------------------------------------------------------------
extern "C" void kernel_launch(void* const* d_in, const int* in_sizes, int n_in,
                              void* d_out, int out_size) {
    const float* x  = (const float*)d_in[0];
    const float* nw = (const float*)d_in[1];
    const float* cw = (const float*)d_in[2];
    const float* cb = (const float*)d_in[3];
    float* out = (float*)d_out;

    static bool attr_set = false;
    if (!attr_set) {
        cudaFuncSetAttribute(fused_kernel, cudaFuncAttributeMaxDynamicSharedMemorySize,
                             SMEM_BYTES);
        attr_set = true;
    }

    dim3 grid(Sn / CS, Bn);    // (512, 4) = 2048 blocks
    fused_kernel<<<grid, 512, SMEM_BYTES>>>(x, nw, cw, cb, out);
}

// round 11
// speedup vs baseline: 1.0821x; 1.0048x over previous
#include <cuda_runtime.h>
#include <cuda_bf16.h>

#define Bn 4
#define Sn 4096
#define Hn 2048
#define H4 (Hn / 4)
#define EPSf 1e-6f

#define CS 13               // s-rows produced per block
#define NROWS (CS + 3)      // 16 = exactly one row per warp

__device__ __forceinline__ float warp_sum(float v) {
#pragma unroll
    for (int o = 16; o; o >>= 1)
        v += __shfl_xor_sync(0xFFFFFFFFu, v, o);
    return v;
}

__device__ __forceinline__ float dot4(const float4 v) {
    return fmaf(v.x, v.x, fmaf(v.y, v.y, fmaf(v.z, v.z, v.w * v.w)));
}

// ---------------------------------------------------------------------------
// Fused RMSNorm + depthwise causal conv1d (K=4) + bias.
// grid = (ceil(S/CS), B) = 1264 blocks, block = 512, occ 2.
// Phase 1: warp w reduces window row w (EXACTLY one full row per warp:
//          balanced, 16-deep independent LDG.128 stream). One barrier.
// Phase 2: thread owns one float4 H-column, rolling 3-deep window (L2
//          re-read), norm_weight folded into taps, streaming stores.
// ---------------------------------------------------------------------------
__global__ __launch_bounds__(512, 2) void fused_kernel(const float* __restrict__ x,
                                                       const float* __restrict__ nw,
                                                       const float* __restrict__ cw,
                                                       const float* __restrict__ cb,
                                                       float*       __restrict__ out) {
    __shared__ float s_ir[NROWS];

    const int b    = blockIdx.y;
    const int s0   = blockIdx.x * CS;
    const int tid  = threadIdx.x;
    const int warp = tid >> 5;
    const int lane = tid & 31;

    const float* xb = x   + (size_t)b * Sn * Hn;
    float*       ob = out + (size_t)b * Sn * Hn;

    // ---- Phase 1: one window row per warp ----
    {
        const int s = s0 - 3 + warp;          // window rows s0-3 .. s0+CS-1
        float a0 = 0.f, a1 = 0.f;
        if (s >= 0 && s < Sn) {
            const float4* xr = reinterpret_cast<const float4*>(xb + (size_t)s * Hn);
#pragma unroll
            for (int i = 0; i < 16; i += 2) {
                float4 v0 = xr[lane + 32 * (i + 0)];
                float4 v1 = xr[lane + 32 * (i + 1)];
                a0 += dot4(v0);
                a1 += dot4(v1);
            }
        }
        float ss = warp_sum(a0 + a1);
        if (lane == 0)
            s_ir[warp] = (s >= 0 && s < Sn) ? rsqrtf(ss * (1.0f / (float)Hn) + EPSf) : 0.0f;
    }

    // ---- per-thread constants (independent of phase 1; overlaps the streams) ----
    const int h4 = tid;                       // 0..511
    const int h  = h4 * 4;
    const float4* cw4 = reinterpret_cast<const float4*>(cw);
    const float4 nwv = __ldg(&reinterpret_cast<const float4*>(nw)[h4]);
    float4 t0 = __ldg(&cw4[h + 0]);
    float4 t1 = __ldg(&cw4[h + 1]);
    float4 t2 = __ldg(&cw4[h + 2]);
    float4 t3 = __ldg(&cw4[h + 3]);
    t0.x *= nwv.x; t0.y *= nwv.x; t0.z *= nwv.x; t0.w *= nwv.x;
    t1.x *= nwv.y; t1.y *= nwv.y; t1.z *= nwv.y; t1.w *= nwv.y;
    t2.x *= nwv.z; t2.y *= nwv.z; t2.z *= nwv.z; t2.w *= nwv.z;
    t3.x *= nwv.w; t3.y *= nwv.w; t3.z *= nwv.w; t3.w *= nwv.w;
    const float4 bias = __ldg(&reinterpret_cast<const float4*>(cb)[h4]);

    __syncthreads();

    // ---- Phase 2: rolling window conv over rows s0 .. s0+CS-1 ----
    float4 xm3, xm2, xm1;
    {
        float4 pre[3];
#pragma unroll
        for (int j = 0; j < 3; j++) {
            const int s = s0 - 3 + j;
            if (s >= 0) {
                float4 v = reinterpret_cast<const float4*>(xb + (size_t)s * Hn)[h4];
                const float r = s_ir[j];
                pre[j].x = v.x * r;
                pre[j].y = v.y * r;
                pre[j].z = v.z * r;
                pre[j].w = v.w * r;
            } else {
                pre[j] = make_float4(0.f, 0.f, 0.f, 0.f);
            }
        }
        xm3 = pre[0]; xm2 = pre[1]; xm1 = pre[2];
    }

#pragma unroll 4
    for (int j = 0; j < CS; j++) {
        const int s = s0 + j;
        if (s >= Sn) break;                   // tail block guard
        float4 v = reinterpret_cast<const float4*>(xb + (size_t)s * Hn)[h4];
        const float r = s_ir[j + 3];
        float4 xn;
        xn.x = v.x * r;
        xn.y = v.y * r;
        xn.z = v.z * r;
        xn.w = v.w * r;

        float4 y;
        y.x = fmaf(t0.x, xm3.x, fmaf(t0.y, xm2.x, fmaf(t0.z, xm1.x, fmaf(t0.w, xn.x, bias.x))));
        y.y = fmaf(t1.x, xm3.y, fmaf(t1.y, xm2.y, fmaf(t1.z, xm1.y, fmaf(t1.w, xn.y, bias.y))));
        y.z = fmaf(t2.x, xm3.z, fmaf(t2.y, xm2.z, fmaf(t2.z, xm1.z, fmaf(t2.w, xn.z, bias.z))));
        y.w = fmaf(t3.x, xm3.w, fmaf(t3.y, xm2.w, fmaf(t3.z, xm1.w, fmaf(t3.w, xn.w, bias.w))));

        // Streaming store: output is never re-read; don't pollute L2.
        __stcs(reinterpret_cast<float4*>(ob + (size_t)s * Hn) + h4, y);

        xm3 = xm2; xm2 = xm1; xm1 = xn;
    }
}

// ---------------------------------------------------------------------------
// Inputs (metadata order): hidden_states, norm_weight, conv_weight, conv_bias
// ---------------------------------------------------------------------------
extern "C" void kernel_launch(void* const* d_in, const int* in_sizes, int n_in,
                              void* d_out, int out_size) {
    const float* x  = (const float*)d_in[0];
    const float* nw = (const float*)d_in[1];
    const float* cw = (const float*)d_in[2];
    const float* cb = (const float*)d_in[3];
    float* out = (float*)d_out;

    dim3 grid((Sn + CS - 1) / CS, Bn);       // (316, 4) = 1264 blocks
    fused_kernel<<<grid, 512>>>(x, nw, cw, cb, out);
}